// round 9
// baseline (speedup 1.0000x reference)
#include <cuda_runtime.h>
#include <cuda_fp16.h>
#include <math.h>
#include <stdint.h>

#define H 224
#define WPAD 256
#define NIMG 1536
#define ZN (1536ULL * 224 * 256)
#define RS 48                 // smem row stride bytes (32 data + 16 pad)
#define AHO 0
#define ALO 6144
#define BHO 12288
#define BLO 17664
#define STG 23040
#define NC 14                 // K chunks of 16

__device__ __half g_Dh[H * WPAD], g_Dl[H * WPAD];
__device__ __half g_Xh[ZN], g_Xl[ZN];
__device__ __half g_Z1h[ZN], g_Z1l[ZN];
__device__ __half g_Z2h[ZN], g_Z2l[ZN];

__global__ void init_D_kernel() {
    int idx = blockIdx.x * blockDim.x + threadIdx.x;
    if (idx >= H * WPAD) return;
    int k = idx >> 8, i = idx & 255;
    double v = 0.0;
    if (i < H) {
        v = cos(3.14159265358979323846 * (2.0 * i + 1.0) * (double)k / (2.0 * H))
          * sqrt(2.0 / (double)H);
        if (k == 0) v *= 0.70710678118654752440;
    }
    float f = (float)v;
    __half h = __float2half_rn(f);
    g_Dh[idx] = h;
    g_Dl[idx] = __float2half_rn(f - __half2float(h));
}

__device__ __forceinline__ uint32_t psplit(float f0, float f1, uint32_t& lo) {
    __half h0 = __float2half_rn(f0), h1 = __float2half_rn(f1);
    __half2 lp = __floats2half2_rn(f0 - __half2float(h0), f1 - __half2float(h1));
    lo = *(uint32_t*)&lp;
    __half2 hp; hp.x = h0; hp.y = h1;
    return *(uint32_t*)&hp;
}

__global__ __launch_bounds__(256)
void kxc_kernel(const float* __restrict__ x) {
    size_t idx4 = ((size_t)blockIdx.x * 256 + threadIdx.x) * 4;
    if (idx4 >= (size_t)NIMG * H * H) return;
    size_t img = idx4 / (H * H);
    int rem = (int)(idx4 - img * (H * H));
    int h = rem / H, w = rem - h * H;
    float4 v = *(const float4*)(x + idx4);
    uint32_t l0, l1;
    uint32_t h0 = psplit(v.x, v.y, l0);
    uint32_t h1 = psplit(v.z, v.w, l1);
    size_t off = (img * H + h) * WPAD + w;
    *(uint2*)(g_Xh + off) = make_uint2(h0, h1);
    *(uint2*)(g_Xl + off) = make_uint2(l0, l1);
}

__device__ __forceinline__ uint32_t smem_u32(const void* p) {
    uint32_t a;
    asm("{ .reg .u64 t; cvta.to.shared.u64 t, %1; cvt.u32.u64 %0, t; }" : "=r"(a) : "l"(p));
    return a;
}
__device__ __forceinline__ void ldsm4(uint32_t* r, uint32_t a) {
    asm volatile("ldmatrix.sync.aligned.m8n8.x4.shared.b16 {%0,%1,%2,%3}, [%4];"
                 : "=r"(r[0]), "=r"(r[1]), "=r"(r[2]), "=r"(r[3]) : "r"(a));
}
__device__ __forceinline__ void ldsm2(uint32_t* r, uint32_t a) {
    asm volatile("ldmatrix.sync.aligned.m8n8.x2.shared.b16 {%0,%1}, [%2];"
                 : "=r"(r[0]), "=r"(r[1]) : "r"(a));
}
__device__ __forceinline__ void mma16816(float* d, const uint32_t* a, const uint32_t* b) {
    asm volatile("mma.sync.aligned.m16n8k16.row.col.f32.f16.f16.f32 "
                 "{%0,%1,%2,%3}, {%4,%5,%6,%7}, {%8,%9}, {%0,%1,%2,%3};"
                 : "+f"(d[0]), "+f"(d[1]), "+f"(d[2]), "+f"(d[3])
                 : "r"(a[0]), "r"(a[1]), "r"(a[2]), "r"(a[3]), "r"(b[0]), "r"(b[1]));
}
__device__ __forceinline__ void cpa16(uint32_t d, const void* s) {
    asm volatile("cp.async.cg.shared.global [%0], [%1], 16;" :: "r"(d), "l"(s));
}

// mode 0: Z1=D.X^T; 1: Z2=D.Z1^T (mask); 2: Z1=D.Z2^T; 3: out=x*(D.Z1^T)
__global__ __launch_bounds__(256, 2)
void gemm_kernel(const float* __restrict__ x, float* __restrict__ fout, int mode) {
    extern __shared__ char sm[];
    const int tid = threadIdx.x, wid = tid >> 5, lane = tid & 31;
    const int img = blockIdx.y;
    const int m0 = (blockIdx.x & 1) * 96, n0 = (blockIdx.x >> 1) * 112;
    const int wm = (wid >> 1) * 32, wn = (wid & 1) * 56;

    const __half *Bh, *Bl;
    __half *Oh, *Ol;
    if (mode == 1)      { Bh = g_Z1h; Bl = g_Z1l; Oh = g_Z2h; Ol = g_Z2l; }
    else if (mode == 2) { Bh = g_Z2h; Bl = g_Z2l; Oh = g_Z1h; Ol = g_Z1l; }
    else if (mode == 3) { Bh = g_Z1h; Bl = g_Z1l; Oh = 0;     Ol = 0;     }
    else                { Bh = g_Xh;  Bl = g_Xl;  Oh = g_Z1h; Ol = g_Z1l; }

    const float* xi = x + (size_t)img * H * H;
    const char* gDh = (const char*)g_Dh;
    const char* gDl = (const char*)g_Dl;
    const char* gBh = (const char*)(Bh + (size_t)img * H * WPAD);
    const char* gBl = (const char*)(Bl + (size_t)img * H * WPAD);

    float acc[2][7][4];
#pragma unroll
    for (int i = 0; i < 2; i++)
#pragma unroll
        for (int j = 0; j < 7; j++)
#pragma unroll
            for (int q = 0; q < 4; q++) acc[i][j][q] = 0.f;

    const uint32_t smb = smem_u32(sm);
    const uint32_t aab = smb + (uint32_t)(wm + (lane & 15)) * RS + (lane >> 4) * 16;
    const uint32_t bab = smb + BHO + (uint32_t)(wn + (lane & 7)) * RS + ((lane >> 3) & 1) * 16;

    const int lr = tid >> 1, lj = (tid & 1) * 16;

    // prologue: issue chunks 0..2
#pragma unroll
    for (int c = 0; c < 3; c++) {
        const uint32_t sb = smb + c * STG;
        const size_t ko = (size_t)c * 32;
        {
            size_t ga = (size_t)(m0 + lr) * 512 + ko + lj;
            cpa16(sb + AHO + lr * RS + lj, gDh + ga);
            cpa16(sb + ALO + lr * RS + lj, gDl + ga);
        }
        if (tid < 224) {
            size_t gb = (size_t)(n0 + lr) * 512 + ko + lj;
            cpa16(sb + BHO + lr * RS + lj, gBh + gb);
            cpa16(sb + BLO + lr * RS + lj, gBl + gb);
        }
        asm volatile("cp.async.commit_group;" ::: "memory");
    }

#pragma unroll 1
    for (int c = 0; c < NC; c++) {
        if (c < NC - 2)      asm volatile("cp.async.wait_group 2;" ::: "memory");
        else if (c == NC - 2) asm volatile("cp.async.wait_group 1;" ::: "memory");
        else                  asm volatile("cp.async.wait_group 0;" ::: "memory");
        __syncthreads();
        if (c + 3 < NC) {
            const uint32_t sb = smb + ((c + 3) & 3) * STG;
            const size_t ko = (size_t)(c + 3) * 32;
            {
                size_t ga = (size_t)(m0 + lr) * 512 + ko + lj;
                cpa16(sb + AHO + lr * RS + lj, gDh + ga);
                cpa16(sb + ALO + lr * RS + lj, gDl + ga);
            }
            if (tid < 224) {
                size_t gb = (size_t)(n0 + lr) * 512 + ko + lj;
                cpa16(sb + BHO + lr * RS + lj, gBh + gb);
                cpa16(sb + BLO + lr * RS + lj, gBl + gb);
            }
            asm volatile("cp.async.commit_group;" ::: "memory");
        }
        // compute chunk c
        const uint32_t off = (c & 3) * STG;
        uint32_t ah[2][4], al[2][4];
#pragma unroll
        for (int i = 0; i < 2; i++) {
            ldsm4(ah[i], aab + off + i * 16 * RS);
            ldsm4(al[i], aab + off + i * 16 * RS + ALO);
        }
#pragma unroll
        for (int j = 0; j < 7; j++) {
            uint32_t bh[2], bl[2];
            ldsm2(bh, bab + off + j * 8 * RS);
            ldsm2(bl, bab + off + j * 8 * RS + (BLO - BHO));
#pragma unroll
            for (int i = 0; i < 2; i++) {
                mma16816(acc[i][j], ah[i], bh);
                mma16816(acc[i][j], ah[i], bl);
                mma16816(acc[i][j], al[i], bh);
            }
        }
    }

    // ---- epilogue ----
#pragma unroll
    for (int i = 0; i < 2; i++) {
#pragma unroll
        for (int j = 0; j < 7; j++) {
            float* d = acc[i][j];
            int m1 = m0 + wm + 16 * i + (lane >> 2);
            int n  = n0 + wn + 8 * j + ((lane & 3) << 1);
            if (mode == 3) {
                const float* xr = xi + (size_t)m1 * H + n;
                float* orow = fout + (size_t)img * H * H + (size_t)m1 * H + n;
                float2 x0 = *(const float2*)xr;
                float2 x1 = *(const float2*)(xr + 8 * H);
                *(float2*)orow = make_float2(x0.x * d[0], x0.y * d[1]);
                *(float2*)(orow + 8 * H) = make_float2(x1.x * d[2], x1.y * d[3]);
            } else {
                float f0 = d[0], f1 = d[1], f2 = d[2], f3 = d[3];
                if (mode == 1 && n < 56) {
                    if (m1 < 56) { f0 = 0.f; f1 = 0.f; }
                    if (m1 + 8 < 56) { f2 = 0.f; f3 = 0.f; }
                }
                uint32_t lo0, lo1;
                uint32_t hi0 = psplit(f0, f1, lo0);
                uint32_t hi1 = psplit(f2, f3, lo1);
                char* oh = (char*)Oh + ((size_t)img * H * WPAD + (size_t)m1 * WPAD + n) * 2;
                char* ol = (char*)Ol + ((size_t)img * H * WPAD + (size_t)m1 * WPAD + n) * 2;
                *(uint32_t*)oh = hi0;
                *(uint32_t*)ol = lo0;
                *(uint32_t*)(oh + 8 * WPAD * 2) = hi1;
                *(uint32_t*)(ol + 8 * WPAD * 2) = lo1;
            }
        }
    }
}

extern "C" void kernel_launch(void* const* d_in, const int* in_sizes, int n_in,
                              void* d_out, int out_size) {
    const float* x = (const float*)d_in[0];
    float* out = (float*)d_out;

    init_D_kernel<<<(H * WPAD + 255) / 256, 256>>>();
    kxc_kernel<<<(int)(((size_t)NIMG * H * H / 4 + 255) / 256), 256>>>(x);

    const int smem = 4 * STG;  // 92160
    cudaFuncSetAttribute(gemm_kernel, cudaFuncAttributeMaxDynamicSharedMemorySize, smem);

    dim3 g(4, NIMG);
    gemm_kernel<<<g, 256, smem>>>(x, out, 0);
    gemm_kernel<<<g, 256, smem>>>(x, out, 1);
    gemm_kernel<<<g, 256, smem>>>(x, out, 2);
    gemm_kernel<<<g, 256, smem>>>(x, out, 3);
}

// round 10
// speedup vs baseline: 1.0334x; 1.0334x over previous
#include <cuda_runtime.h>
#include <cuda_fp16.h>
#include <math.h>
#include <stdint.h>

#define H 224
#define WPAD 256
#define NIMG 1536
#define ZN (1536ULL * 224 * 256)
#define RS 80
#define AHS 0
#define ALS 10240
#define BHS 20480
#define BLS 38400
#define STG 56320
#define NC 7

__device__ __half g_Dh[H * WPAD], g_Dl[H * WPAD];
__device__ __half g_Xh[ZN], g_Xl[ZN];
__device__ __half g_Z1h[ZN], g_Z1l[ZN];
__device__ __half g_Z2h[ZN], g_Z2l[ZN];

__global__ void init_D_kernel() {
    int idx = blockIdx.x * blockDim.x + threadIdx.x;
    if (idx >= H * WPAD) return;
    int k = idx >> 8, i = idx & 255;
    double v = 0.0;
    if (i < H) {
        v = cos(3.14159265358979323846 * (2.0 * i + 1.0) * (double)k / (2.0 * H))
          * sqrt(2.0 / (double)H);
        if (k == 0) v *= 0.70710678118654752440;
    }
    float f = (float)v;
    __half h = __float2half_rn(f);
    g_Dh[idx] = h;
    g_Dl[idx] = __float2half_rn(f - __half2float(h));
}

__device__ __forceinline__ uint32_t psplit(float f0, float f1, uint32_t& lo) {
    __half h0 = __float2half_rn(f0), h1 = __float2half_rn(f1);
    __half2 lp = __floats2half2_rn(f0 - __half2float(h0), f1 - __half2float(h1));
    lo = *(uint32_t*)&lp;
    __half2 hp; hp.x = h0; hp.y = h1;
    return *(uint32_t*)&hp;
}

__global__ __launch_bounds__(256)
void kxc_kernel(const float* __restrict__ x) {
    size_t idx4 = ((size_t)blockIdx.x * 256 + threadIdx.x) * 4;
    if (idx4 >= (size_t)NIMG * H * H) return;
    size_t img = idx4 / (H * H);
    int rem = (int)(idx4 - img * (H * H));
    int h = rem / H, w = rem - h * H;
    float4 v = *(const float4*)(x + idx4);
    uint32_t l0, l1;
    uint32_t h0 = psplit(v.x, v.y, l0);
    uint32_t h1 = psplit(v.z, v.w, l1);
    size_t off = (img * H + h) * WPAD + w;
    *(uint2*)(g_Xh + off) = make_uint2(h0, h1);
    *(uint2*)(g_Xl + off) = make_uint2(l0, l1);
}

__device__ __forceinline__ uint32_t smem_u32(const void* p) {
    uint32_t a;
    asm("{ .reg .u64 t; cvta.to.shared.u64 t, %1; cvt.u32.u64 %0, t; }" : "=r"(a) : "l"(p));
    return a;
}
__device__ __forceinline__ void ldsm4(uint32_t* r, uint32_t a) {
    asm volatile("ldmatrix.sync.aligned.m8n8.x4.shared.b16 {%0,%1,%2,%3}, [%4];"
                 : "=r"(r[0]), "=r"(r[1]), "=r"(r[2]), "=r"(r[3]) : "r"(a));
}
__device__ __forceinline__ void ldsm2(uint32_t* r, uint32_t a) {
    asm volatile("ldmatrix.sync.aligned.m8n8.x2.shared.b16 {%0,%1}, [%2];"
                 : "=r"(r[0]), "=r"(r[1]) : "r"(a));
}
__device__ __forceinline__ void mma16816(float* d, const uint32_t* a, const uint32_t* b) {
    asm volatile("mma.sync.aligned.m16n8k16.row.col.f32.f16.f16.f32 "
                 "{%0,%1,%2,%3}, {%4,%5,%6,%7}, {%8,%9}, {%0,%1,%2,%3};"
                 : "+f"(d[0]), "+f"(d[1]), "+f"(d[2]), "+f"(d[3])
                 : "r"(a[0]), "r"(a[1]), "r"(a[2]), "r"(a[3]), "r"(b[0]), "r"(b[1]));
}
__device__ __forceinline__ void cpa16(uint32_t d, const void* s) {
    asm volatile("cp.async.cg.shared.global [%0], [%1], 16;" :: "r"(d), "l"(s));
}

// mode 0: Z1=D.X^T; 1: Z2=D.Z1^T (mask); 2: Z1=D.Z2^T; 3: out=x*(D.Z1^T)
__global__ __launch_bounds__(512, 1)
void gemm_kernel(const float* __restrict__ x, float* __restrict__ fout, int mode) {
    extern __shared__ char sm[];
    const int tid = threadIdx.x, wid = tid >> 5, lane = tid & 31;
    const int img = blockIdx.y;
    const int m0 = blockIdx.x * 96;
    const int wm = (wid & 3) * 32, wn = (wid >> 2) * 56;

    const __half *Bh, *Bl;
    __half *Oh, *Ol;
    if (mode == 1)      { Bh = g_Z1h; Bl = g_Z1l; Oh = g_Z2h; Ol = g_Z2l; }
    else if (mode == 2) { Bh = g_Z2h; Bl = g_Z2l; Oh = g_Z1h; Ol = g_Z1l; }
    else if (mode == 3) { Bh = g_Z1h; Bl = g_Z1l; Oh = 0;     Ol = 0;     }
    else                { Bh = g_Xh;  Bl = g_Xl;  Oh = g_Z1h; Ol = g_Z1l; }

    const float* xi = x + (size_t)img * H * H;
    const char* gDh = (const char*)g_Dh;
    const char* gDl = (const char*)g_Dl;
    const char* gBh = (const char*)(Bh + (size_t)img * H * WPAD);
    const char* gBl = (const char*)(Bl + (size_t)img * H * WPAD);

    float acc[2][7][4];
#pragma unroll
    for (int i = 0; i < 2; i++)
#pragma unroll
        for (int j = 0; j < 7; j++)
#pragma unroll
            for (int q = 0; q < 4; q++) acc[i][j][q] = 0.f;

    const uint32_t smb = smem_u32(sm);
    const uint32_t aab = smb + AHS + (uint32_t)(wm + (lane & 15)) * RS + (lane >> 4) * 16;
    const uint32_t bab = smb + BHS + (uint32_t)(wn + (lane & 7)) * RS + ((lane >> 3) & 1) * 16;

    const int ar = tid >> 2, aj = (tid & 3) * 16;

    // prologue: chunks 0,1 into stages 0,1
#pragma unroll
    for (int c = 0; c < 2; c++) {
        const uint32_t sb = smb + c * STG;
        const int ko = c * 64;
        {
            size_t ga = (size_t)(m0 + ar) * 512 + ko + aj;
            cpa16(sb + AHS + ar * RS + aj, gDh + ga);
            cpa16(sb + ALS + ar * RS + aj, gDl + ga);
        }
#pragma unroll
        for (int p = 0; p < 2; p++) {
            int idx = tid + p * 512;
            if (idx < 896) {
                int r = idx >> 2, j = (idx & 3) * 16;
                size_t gb = (size_t)r * 512 + ko + j;
                cpa16(sb + BHS + r * RS + j, gBh + gb);
                cpa16(sb + BLS + r * RS + j, gBl + gb);
            }
        }
        asm volatile("cp.async.commit_group;" ::: "memory");
    }

#pragma unroll 1
    for (int c = 0; c < NC; c++) {
        if (c < NC - 1) asm volatile("cp.async.wait_group 1;" ::: "memory");
        else            asm volatile("cp.async.wait_group 0;" ::: "memory");
        __syncthreads();
        if (c + 2 < NC) {
            const uint32_t sb = smb + ((c + 2) % 3) * STG;
            const int ko = (c + 2) * 64;
            {
                size_t ga = (size_t)(m0 + ar) * 512 + ko + aj;
                cpa16(sb + AHS + ar * RS + aj, gDh + ga);
                cpa16(sb + ALS + ar * RS + aj, gDl + ga);
            }
#pragma unroll
            for (int p = 0; p < 2; p++) {
                int idx = tid + p * 512;
                if (idx < 896) {
                    int r = idx >> 2, j = (idx & 3) * 16;
                    size_t gb = (size_t)r * 512 + ko + j;
                    cpa16(sb + BHS + r * RS + j, gBh + gb);
                    cpa16(sb + BLS + r * RS + j, gBl + gb);
                }
            }
            asm volatile("cp.async.commit_group;" ::: "memory");
        }
        // compute chunk c from stage c%3
        const uint32_t off = (c % 3) * STG;
#pragma unroll
        for (int ks = 0; ks < 2; ks++) {
            const uint32_t ko = ks * 32;
            uint32_t ah[2][4], al[2][4];
#pragma unroll
            for (int i = 0; i < 2; i++) {
                ldsm4(ah[i], aab + off + i * 16 * RS + ko);
                ldsm4(al[i], aab + off + i * 16 * RS + ko + ALS);
            }
#pragma unroll
            for (int j = 0; j < 7; j++) {
                uint32_t bh[2], bl[2];
                ldsm2(bh, bab + off + j * 8 * RS + ko);
                ldsm2(bl, bab + off + j * 8 * RS + ko + (BLS - BHS));
#pragma unroll
                for (int i = 0; i < 2; i++) {
                    mma16816(acc[i][j], ah[i], bh);
                    mma16816(acc[i][j], ah[i], bl);
                    mma16816(acc[i][j], al[i], bh);
                }
            }
        }
    }

    // ---- epilogue ----
#pragma unroll
    for (int i = 0; i < 2; i++) {
#pragma unroll
        for (int j = 0; j < 7; j++) {
            float* d = acc[i][j];
            int m1 = m0 + wm + 16 * i + (lane >> 2);
            int n  = wn + 8 * j + ((lane & 3) << 1);
            if (mode == 3) {
                const float* xr = xi + (size_t)m1 * H + n;
                float* orow = fout + (size_t)img * H * H + (size_t)m1 * H + n;
                float2 x0 = *(const float2*)xr;
                float2 x1 = *(const float2*)(xr + 8 * H);
                *(float2*)orow = make_float2(x0.x * d[0], x0.y * d[1]);
                *(float2*)(orow + 8 * H) = make_float2(x1.x * d[2], x1.y * d[3]);
            } else {
                float f0 = d[0], f1 = d[1], f2 = d[2], f3 = d[3];
                if (mode == 1 && n < 56) {
                    if (m1 < 56) { f0 = 0.f; f1 = 0.f; }
                    if (m1 + 8 < 56) { f2 = 0.f; f3 = 0.f; }
                }
                uint32_t lo0, lo1;
                uint32_t hi0 = psplit(f0, f1, lo0);
                uint32_t hi1 = psplit(f2, f3, lo1);
                char* oh = (char*)Oh + ((size_t)img * H * WPAD + (size_t)m1 * WPAD + n) * 2;
                char* ol = (char*)Ol + ((size_t)img * H * WPAD + (size_t)m1 * WPAD + n) * 2;
                *(uint32_t*)oh = hi0;
                *(uint32_t*)ol = lo0;
                *(uint32_t*)(oh + 8 * WPAD * 2) = hi1;
                *(uint32_t*)(ol + 8 * WPAD * 2) = lo1;
            }
        }
    }
}

extern "C" void kernel_launch(void* const* d_in, const int* in_sizes, int n_in,
                              void* d_out, int out_size) {
    const float* x = (const float*)d_in[0];
    float* out = (float*)d_out;

    init_D_kernel<<<(H * WPAD + 255) / 256, 256>>>();
    kxc_kernel<<<(int)(((size_t)NIMG * H * H / 4 + 255) / 256), 256>>>(x);

    const int smem = 3 * STG;  // 168960
    cudaFuncSetAttribute(gemm_kernel, cudaFuncAttributeMaxDynamicSharedMemorySize, smem);

    dim3 g(2, NIMG);
    gemm_kernel<<<g, 512, smem>>>(x, out, 0);
    gemm_kernel<<<g, 512, smem>>>(x, out, 1);
    gemm_kernel<<<g, 512, smem>>>(x, out, 2);
    gemm_kernel<<<g, 512, smem>>>(x, out, 3);
}

// round 11
// speedup vs baseline: 1.1617x; 1.1242x over previous
#include <cuda_runtime.h>
#include <cuda_fp16.h>
#include <math.h>
#include <stdint.h>

#define H 224
#define NIMG 1536
#define RS 80
#define AHS 0
#define ALS 10240
#define BHS 20480
#define BLS 38400
#define STG 56320

__device__ float g_D[H * H];
__device__ __half g_G1h[288 * 256], g_G1l[288 * 256];      // [A; U; 0] padded
__device__ __half g_Cph[224 * 64], g_Cpl[224 * 64];        // [C | 0]
__device__ __half g_Xh[NIMG * 224ULL * 256], g_Xl[NIMG * 224ULL * 256];
__device__ __half g_Ph[NIMG * 224ULL * 256], g_Pl[NIMG * 224ULL * 256];
__device__ __half g_Th[NIMG * 56ULL * 256],  g_Tl[NIMG * 56ULL * 256];
__device__ __half g_Wh[NIMG * 224ULL * 64],  g_Wl[NIMG * 224ULL * 64];

__global__ void init_D_kernel() {
    int idx = blockIdx.x * blockDim.x + threadIdx.x;
    if (idx >= H * H) return;
    int k = idx / H, i = idx - k * H;
    double v = cos(3.14159265358979323846 * (2.0 * i + 1.0) * (double)k / (2.0 * H))
             * sqrt(2.0 / (double)H);
    if (k == 0) v *= 0.70710678118654752440;
    g_D[idx] = (float)v;
}

__device__ __forceinline__ void sp1(float v, __half* ph, __half* pl) {
    __half h = __float2half_rn(v);
    *ph = h;
    *pl = __float2half_rn(v - __half2float(h));
}

// block i of 288: row i of g_G1 (A=D^2 / U / 0) + row i of g_Cp (i<224)
__global__ __launch_bounds__(256)
void init_static_kernel() {
    __shared__ float srow[H];
    const int i = blockIdx.x, tid = threadIdx.x;
    if (i < 224)
        for (int k = tid; k < H; k += 256) srow[k] = g_D[i * H + k];
    __syncthreads();
    int j = tid;  // 0..255
    float v = 0.f;
    if (i < 224 && j < 224) {
        for (int k = 0; k < H; k++) v += srow[k] * g_D[k * H + j];
    } else if (i >= 224 && i < 280 && j < 224) {
        v = g_D[(i - 224) * H + j];
    }
    sp1(v, &g_G1h[i * 256 + j], &g_G1l[i * 256 + j]);
    if (i < 224 && tid < 64) {
        float c = (tid < 56) ? g_D[i * H + tid] : 0.f;
        sp1(c, &g_Cph[i * 64 + tid], &g_Cpl[i * 64 + tid]);
    }
}

__device__ __forceinline__ uint32_t psplit(float f0, float f1, uint32_t& lo) {
    __half h0 = __float2half_rn(f0), h1 = __float2half_rn(f1);
    __half2 lp = __floats2half2_rn(f0 - __half2float(h0), f1 - __half2float(h1));
    lo = *(uint32_t*)&lp;
    __half2 hp; hp.x = h0; hp.y = h1;
    return *(uint32_t*)&hp;
}

__global__ __launch_bounds__(256)
void kxc_kernel(const float* __restrict__ x) {
    size_t idx4 = ((size_t)blockIdx.x * 256 + threadIdx.x) * 4;
    if (idx4 >= (size_t)NIMG * H * H) return;
    size_t img = idx4 / (H * H);
    int rem = (int)(idx4 - img * (H * H));
    int h = rem / H, w = rem - h * H;
    float4 v = *(const float4*)(x + idx4);
    uint32_t l0, l1;
    uint32_t h0 = psplit(v.x, v.y, l0);
    uint32_t h1 = psplit(v.z, v.w, l1);
    size_t off = (img * H + h) * 256 + w;
    *(uint2*)(g_Xh + off) = make_uint2(h0, h1);
    *(uint2*)(g_Xl + off) = make_uint2(l0, l1);
}

__device__ __forceinline__ uint32_t smem_u32(const void* p) {
    uint32_t a;
    asm("{ .reg .u64 t; cvta.to.shared.u64 t, %1; cvt.u32.u64 %0, t; }" : "=r"(a) : "l"(p));
    return a;
}
__device__ __forceinline__ void ldsm4(uint32_t* r, uint32_t a) {
    asm volatile("ldmatrix.sync.aligned.m8n8.x4.shared.b16 {%0,%1,%2,%3}, [%4];"
                 : "=r"(r[0]), "=r"(r[1]), "=r"(r[2]), "=r"(r[3]) : "r"(a));
}
__device__ __forceinline__ void ldsm2(uint32_t* r, uint32_t a) {
    asm volatile("ldmatrix.sync.aligned.m8n8.x2.shared.b16 {%0,%1}, [%2];"
                 : "=r"(r[0]), "=r"(r[1]) : "r"(a));
}
__device__ __forceinline__ void mma16816(float* d, const uint32_t* a, const uint32_t* b) {
    asm volatile("mma.sync.aligned.m16n8k16.row.col.f32.f16.f16.f32 "
                 "{%0,%1,%2,%3}, {%4,%5,%6,%7}, {%8,%9}, {%0,%1,%2,%3};"
                 : "+f"(d[0]), "+f"(d[1]), "+f"(d[2]), "+f"(d[3])
                 : "r"(a[0]), "r"(a[1]), "r"(a[2]), "r"(a[3]), "r"(b[0]), "r"(b[1]));
}
__device__ __forceinline__ void cpa16(uint32_t d, const void* s) {
    asm volatile("cp.async.cg.shared.global [%0], [%1], 16;" :: "r"(d), "l"(s));
}

__device__ __forceinline__ void store_PT(int img, int row, int n, float f0, float f1) {
    __half *oh, *ol;
    size_t base;
    if (row < 224)      { base = ((size_t)img * 224 + row) * 256 + n; oh = g_Ph; ol = g_Pl; }
    else if (row < 280) { base = ((size_t)img * 56 + (row - 224)) * 256 + n; oh = g_Th; ol = g_Tl; }
    else return;
    uint32_t lo;
    uint32_t hi = psplit(f0, f1, lo);
    *(uint32_t*)((char*)oh + base * 2) = hi;
    *(uint32_t*)((char*)ol + base * 2) = lo;
}

// mode 0 (K1): P'=[A;U].X^T, M-tiles {0,96,160}, NC=7; writes P + T
// mode 1 (K4): G = A.P^T + W.C^T (K=288, NC=9), out = x*G, M-tiles {0,96}
__global__ __launch_bounds__(512, 1)
void gemm_kernel(const float* __restrict__ x, float* __restrict__ fout, int mode) {
    extern __shared__ char sm[];
    const int tid = threadIdx.x, wid = tid >> 5, lane = tid & 31;
    const int img = blockIdx.y;
    const int m0 = blockIdx.x * 96;
    const int wm = (wid & 3) * 32, wn = (wid >> 2) * 56;
    const int NC = (mode == 0) ? 7 : 9;

    const char* gBh;
    const char* gBl;
    if (mode == 0) {
        gBh = (const char*)(g_Xh + (size_t)img * 224 * 256);
        gBl = (const char*)(g_Xl + (size_t)img * 224 * 256);
    } else {
        gBh = (const char*)(g_Ph + (size_t)img * 224 * 256);
        gBl = (const char*)(g_Pl + (size_t)img * 224 * 256);
    }
    const char* gWh = (const char*)(g_Wh + (size_t)img * 224 * 64);
    const char* gWl = (const char*)(g_Wl + (size_t)img * 224 * 64);
    const float* xi = x + (size_t)img * H * H;

    float acc[2][7][4];
#pragma unroll
    for (int i = 0; i < 2; i++)
#pragma unroll
        for (int j = 0; j < 7; j++)
#pragma unroll
            for (int q = 0; q < 4; q++) acc[i][j][q] = 0.f;

    const uint32_t smb = smem_u32(sm);
    const uint32_t aab = smb + AHS + (uint32_t)(wm + (lane & 15)) * RS + (lane >> 4) * 16;
    const uint32_t bab = smb + BHS + (uint32_t)(wn + (lane & 7)) * RS + ((lane >> 3) & 1) * 16;
    const int ar = tid >> 2, aj = (tid & 3) * 16;

#define LOAD_CHUNK(CC, SB) do {                                               \
    const int c_ = (CC); const uint32_t sb_ = (SB);                           \
    const char *Ah_, *Al_, *Bh_, *Bl_; size_t arw_, brw_; int ko_;            \
    if (c_ < 7) { Ah_ = (const char*)g_G1h; Al_ = (const char*)g_G1l;         \
        arw_ = 512; Bh_ = gBh; Bl_ = gBl; brw_ = 512; ko_ = c_ * 64; }        \
    else { Ah_ = gWh; Al_ = gWl; arw_ = 128;                                  \
        Bh_ = (const char*)g_Cph; Bl_ = (const char*)g_Cpl; brw_ = 128;       \
        ko_ = (c_ - 7) * 64; }                                                \
    { size_t ga = (size_t)(m0 + ar) * arw_ + ko_ + aj;                        \
      cpa16(sb_ + AHS + ar * RS + aj, Ah_ + ga);                              \
      cpa16(sb_ + ALS + ar * RS + aj, Al_ + ga); }                            \
    _Pragma("unroll")                                                         \
    for (int p_ = 0; p_ < 2; p_++) {                                          \
        int idx_ = tid + p_ * 512;                                            \
        if (idx_ < 896) {                                                     \
            int r_ = idx_ >> 2, j_ = (idx_ & 3) * 16;                         \
            size_t gb = (size_t)r_ * brw_ + ko_ + j_;                         \
            cpa16(sb_ + BHS + r_ * RS + j_, Bh_ + gb);                        \
            cpa16(sb_ + BLS + r_ * RS + j_, Bl_ + gb);                        \
        }                                                                     \
    }                                                                         \
    asm volatile("cp.async.commit_group;" ::: "memory");                      \
} while (0)

    LOAD_CHUNK(0, smb);
    LOAD_CHUNK(1, smb + STG);

#pragma unroll 1
    for (int c = 0; c < NC; c++) {
        if (c < NC - 1) asm volatile("cp.async.wait_group 1;" ::: "memory");
        else            asm volatile("cp.async.wait_group 0;" ::: "memory");
        __syncthreads();
        if (c + 2 < NC) LOAD_CHUNK(c + 2, smb + ((c + 2) % 3) * STG);

        const uint32_t off = (c % 3) * STG;
#pragma unroll
        for (int ks = 0; ks < 2; ks++) {
            const uint32_t ko = ks * 32;
            uint32_t ah[2][4], al[2][4];
#pragma unroll
            for (int i = 0; i < 2; i++) {
                ldsm4(ah[i], aab + off + i * 16 * RS + ko);
                ldsm4(al[i], aab + off + i * 16 * RS + ko + ALS);
            }
#pragma unroll
            for (int j = 0; j < 7; j++) {
                uint32_t bh[2], bl[2];
                ldsm2(bh, bab + off + j * 8 * RS + ko);
                ldsm2(bl, bab + off + j * 8 * RS + ko + (BLS - BHS));
#pragma unroll
                for (int i = 0; i < 2; i++) {
                    mma16816(acc[i][j], ah[i], bh);
                    mma16816(acc[i][j], ah[i], bl);
                    mma16816(acc[i][j], al[i], bh);
                }
            }
        }
    }

#pragma unroll
    for (int i = 0; i < 2; i++) {
#pragma unroll
        for (int j = 0; j < 7; j++) {
            float* d = acc[i][j];
            int m1 = m0 + wm + 16 * i + (lane >> 2);
            int n  = wn + 8 * j + ((lane & 3) << 1);
            if (mode == 1) {
                const float* xr = xi + (size_t)m1 * H + n;
                float* orow = fout + (size_t)img * H * H + (size_t)m1 * H + n;
                float2 x0 = *(const float2*)xr;
                float2 x1 = *(const float2*)(xr + 8 * H);
                *(float2*)orow = make_float2(x0.x * d[0], x0.y * d[1]);
                *(float2*)(orow + 8 * H) = make_float2(x1.x * d[2], x1.y * d[3]);
            } else {
                store_PT(img, m1, n, d[0], d[1]);
                store_PT(img, m1 + 8, n, d[2], d[3]);
            }
        }
    }
}

// WK: per image, fp32: M2 = U.T^T (56x56), W = -C.M2 -> g_W (split, cols 56-63 = 0)
#define SU 228
#define STT 60
#define SMM 57
#define SCC 60
__global__ __launch_bounds__(256, 1)
void wk_kernel() {
    extern __shared__ float smw[];
    float* sU = smw;                 // 56*SU
    float* sT = sU + 56 * SU;        // 224*STT  (t[h][l] = T[l][h])
    float* sM = sT + 224 * STT;      // 56*SMM
    float* sC = sM + 56 * SMM;       // 224*SCC
    const int tid = threadIdx.x, wp = tid >> 5, ln = tid & 31;
    const int img = blockIdx.x;

    for (int idx = tid; idx < 56 * H; idx += 256) {
        int k = idx / H, w = idx - k * H;
        sU[k * SU + w] = g_D[idx];
    }
    for (int idx = tid; idx < H * 56; idx += 256) {
        int i = idx / 56, k = idx - i * 56;
        sC[i * SCC + k] = g_D[i * H + k];
    }
    const __half* Th = g_Th + (size_t)img * 56 * 256;
    const __half* Tl = g_Tl + (size_t)img * 56 * 256;
    for (int idx = tid; idx < 56 * H; idx += 256) {
        int l = idx / H, h = idx - l * H;
        float v = __half2float(Th[l * 256 + h]) + __half2float(Tl[l * 256 + h]);
        sT[h * STT + l] = v;
    }
    __syncthreads();

    // stage 2: M[k][l] = sum_h U[k][h] * t[h][l]
    {
        const int k0 = wp * 7;
        float a0[7], a1[7];
#pragma unroll
        for (int ki = 0; ki < 7; ki++) { a0[ki] = 0.f; a1[ki] = 0.f; }
#pragma unroll 1
        for (int h4 = 0; h4 < 56; h4++) {
            const int h = h4 * 4;
            float4 u[7];
#pragma unroll
            for (int ki = 0; ki < 7; ki++)
                u[ki] = *reinterpret_cast<const float4*>(&sU[(k0 + ki) * SU + h]);
            const float* up = reinterpret_cast<const float*>(u);
#pragma unroll
            for (int dh = 0; dh < 4; dh++) {
                float t0 = sT[(h + dh) * STT + ln];
                float t1 = (ln < 24) ? sT[(h + dh) * STT + 32 + ln] : 0.f;
#pragma unroll
                for (int ki = 0; ki < 7; ki++) {
                    float uv = up[ki * 4 + dh];
                    a0[ki] += uv * t0;
                    a1[ki] += uv * t1;
                }
            }
        }
#pragma unroll
        for (int ki = 0; ki < 7; ki++) {
            sM[(k0 + ki) * SMM + ln] = a0[ki];
            if (ln < 24) sM[(k0 + ki) * SMM + 32 + ln] = a1[ki];
        }
    }
    __syncthreads();

    // stage 3: W[i][l] = sum_k C[i][k]*M[k][l]; write -W split, pad zeros
    __half* Wh = g_Wh + (size_t)img * 224 * 64;
    __half* Wl = g_Wl + (size_t)img * 224 * 64;
#pragma unroll 1
    for (int it = 0; it < 4; it++) {
        const int i0 = wp * 28 + it * 7;
        float a0[7], a1[7];
#pragma unroll
        for (int ii = 0; ii < 7; ii++) { a0[ii] = 0.f; a1[ii] = 0.f; }
#pragma unroll 1
        for (int k4 = 0; k4 < 14; k4++) {
            const int k = k4 * 4;
            float4 u[7];
#pragma unroll
            for (int ii = 0; ii < 7; ii++)
                u[ii] = *reinterpret_cast<const float4*>(&sC[(i0 + ii) * SCC + k]);
            const float* up = reinterpret_cast<const float*>(u);
#pragma unroll
            for (int dk = 0; dk < 4; dk++) {
                float m0v = sM[(k + dk) * SMM + ln];
                float m1v = (ln < 24) ? sM[(k + dk) * SMM + 32 + ln] : 0.f;
#pragma unroll
                for (int ii = 0; ii < 7; ii++) {
                    float uv = up[ii * 4 + dk];
                    a0[ii] += uv * m0v;
                    a1[ii] += uv * m1v;
                }
            }
        }
#pragma unroll
        for (int ii = 0; ii < 7; ii++) {
            sp1(-a0[ii], &Wh[(i0 + ii) * 64 + ln], &Wl[(i0 + ii) * 64 + ln]);
            if (ln < 24) sp1(-a1[ii], &Wh[(i0 + ii) * 64 + 32 + ln], &Wl[(i0 + ii) * 64 + 32 + ln]);
        }
    }
    // zero pad cols 56..63
    for (int idx = tid; idx < 224 * 8; idx += 256) {
        int r = idx >> 3, cz = 56 + (idx & 7);
        Wh[r * 64 + cz] = __float2half_rn(0.f);
        Wl[r * 64 + cz] = __float2half_rn(0.f);
    }
}

extern "C" void kernel_launch(void* const* d_in, const int* in_sizes, int n_in,
                              void* d_out, int out_size) {
    const float* x = (const float*)d_in[0];
    float* out = (float*)d_out;

    init_D_kernel<<<(H * H + 255) / 256, 256>>>();
    init_static_kernel<<<288, 256>>>();
    kxc_kernel<<<(int)(((size_t)NIMG * H * H / 4 + 255) / 256), 256>>>(x);

    const int smem = 3 * STG;  // 168960
    cudaFuncSetAttribute(gemm_kernel, cudaFuncAttributeMaxDynamicSharedMemorySize, smem);
    const int smw = (56 * SU + 224 * STT + 56 * SMM + 224 * SCC) * 4;  // 171360
    cudaFuncSetAttribute(wk_kernel, cudaFuncAttributeMaxDynamicSharedMemorySize, smw);

    gemm_kernel<<<dim3(3, NIMG), 512, smem>>>(x, out, 0);
    wk_kernel<<<NIMG, 256, smw>>>();
    gemm_kernel<<<dim3(2, NIMG), 512, smem>>>(x, out, 1);
}

// round 13
// speedup vs baseline: 1.2767x; 1.0990x over previous
#include <cuda_runtime.h>
#include <cuda_fp16.h>
#include <math.h>
#include <stdint.h>

#define H 224
#define NIMG 1536
#define ALS 5120
#define BOFF 10240
#define SST 49664          // stage: A 2*5120 + B 224*176

__device__ float g_D[H * H];
__device__ __half g_G1h[288 * 256], g_G1l[288 * 256];      // [A; U; 0]
__device__ __half g_Cph[224 * 64], g_Cpl[224 * 64];        // [C | 0]
__device__ __half g_Xh[NIMG * 224ULL * 256], g_Xl[NIMG * 224ULL * 256];
__device__ __half g_Ph[NIMG * 224ULL * 256], g_Pl[NIMG * 224ULL * 256];
__device__ __half g_Th[NIMG * 56ULL * 256],  g_Tl[NIMG * 56ULL * 256];
__device__ __half g_Wh[NIMG * 224ULL * 64],  g_Wl[NIMG * 224ULL * 64];

__global__ void init_D_kernel() {
    int idx = blockIdx.x * blockDim.x + threadIdx.x;
    if (idx >= H * H) return;
    int k = idx / H, i = idx - k * H;
    double v = cos(3.14159265358979323846 * (2.0 * i + 1.0) * (double)k / (2.0 * H))
             * sqrt(2.0 / (double)H);
    if (k == 0) v *= 0.70710678118654752440;
    g_D[idx] = (float)v;
}

__device__ __forceinline__ void sp1(float v, __half* ph, __half* pl) {
    __half h = __float2half_rn(v);
    *ph = h;
    *pl = __float2half_rn(v - __half2float(h));
}

__global__ __launch_bounds__(256)
void init_static_kernel() {
    __shared__ float srow[H];
    const int i = blockIdx.x, tid = threadIdx.x;
    if (i < 224)
        for (int k = tid; k < H; k += 256) srow[k] = g_D[i * H + k];
    __syncthreads();
    int j = tid;
    float v = 0.f;
    if (i < 224 && j < 224) {
        for (int k = 0; k < H; k++) v += srow[k] * g_D[k * H + j];
    } else if (i >= 224 && i < 280 && j < 224) {
        v = g_D[(i - 224) * H + j];
    }
    sp1(v, &g_G1h[i * 256 + j], &g_G1l[i * 256 + j]);
    if (i < 224 && tid < 64) {
        float c = (tid < 56) ? g_D[i * H + tid] : 0.f;
        sp1(c, &g_Cph[i * 64 + tid], &g_Cpl[i * 64 + tid]);
    }
}

__device__ __forceinline__ uint32_t psplit(float f0, float f1, uint32_t& lo) {
    __half h0 = __float2half_rn(f0), h1 = __float2half_rn(f1);
    __half2 lp = __floats2half2_rn(f0 - __half2float(h0), f1 - __half2float(h1));
    lo = *(uint32_t*)&lp;
    __half2 hp; hp.x = h0; hp.y = h1;
    return *(uint32_t*)&hp;
}

__global__ __launch_bounds__(256)
void kxc_kernel(const float* __restrict__ x) {
    size_t idx4 = ((size_t)blockIdx.x * 256 + threadIdx.x) * 4;
    if (idx4 >= (size_t)NIMG * H * H) return;
    size_t img = idx4 / (H * H);
    int rem = (int)(idx4 - img * (H * H));
    int h = rem / H, w = rem - h * H;
    float4 v = *(const float4*)(x + idx4);
    uint32_t l0, l1;
    uint32_t h0 = psplit(v.x, v.y, l0);
    uint32_t h1 = psplit(v.z, v.w, l1);
    size_t off = (img * H + h) * 256 + w;
    *(uint2*)(g_Xh + off) = make_uint2(h0, h1);
    *(uint2*)(g_Xl + off) = make_uint2(l0, l1);
}

__device__ __forceinline__ uint32_t smem_u32(const void* p) {
    uint32_t a;
    asm("{ .reg .u64 t; cvta.to.shared.u64 t, %1; cvt.u32.u64 %0, t; }" : "=r"(a) : "l"(p));
    return a;
}
__device__ __forceinline__ void ldsm4(uint32_t* r, uint32_t a) {
    asm volatile("ldmatrix.sync.aligned.m8n8.x4.shared.b16 {%0,%1,%2,%3}, [%4];"
                 : "=r"(r[0]), "=r"(r[1]), "=r"(r[2]), "=r"(r[3]) : "r"(a));
}
__device__ __forceinline__ void mma16816(float* d, const uint32_t* a, const uint32_t* b) {
    asm volatile("mma.sync.aligned.m16n8k16.row.col.f32.f16.f16.f32 "
                 "{%0,%1,%2,%3}, {%4,%5,%6,%7}, {%8,%9}, {%0,%1,%2,%3};"
                 : "+f"(d[0]), "+f"(d[1]), "+f"(d[2]), "+f"(d[3])
                 : "r"(a[0]), "r"(a[1]), "r"(a[2]), "r"(a[3]), "r"(b[0]), "r"(b[1]));
}
__device__ __forceinline__ void cpa16(uint32_t d, const void* s) {
    asm volatile("cp.async.cg.shared.global [%0], [%1], 16;" :: "r"(d), "l"(s));
}

__device__ __forceinline__ void store_PT(int img, int row, int n, float f0, float f1) {
    __half *oh, *ol;
    size_t base;
    if (row < 224)      { base = ((size_t)img * 224 + row) * 256 + n; oh = g_Ph; ol = g_Pl; }
    else if (row < 280) { base = ((size_t)img * 56 + (row - 224)) * 256 + n; oh = g_Th; ol = g_Tl; }
    else return;
    uint32_t lo;
    uint32_t hi = psplit(f0, f1, lo);
    *(uint32_t*)((char*)oh + base * 2) = hi;
    *(uint32_t*)((char*)ol + base * 2) = lo;
}

// mode 0 (K1): P'=[A;U].X^T, 5 m-tiles of 64, NC=7 -> P + T
// mode 1 (K4): G=A.P^T + W.C^T, 4 m-tiles of 64, NC=9 -> out = x*G
__global__ __launch_bounds__(256, 2)
void gemm_kernel(const float* __restrict__ x, float* __restrict__ fout, int mode) {
    extern __shared__ char sm[];
    const int tid = threadIdx.x, wid = tid >> 5, lane = tid & 31;
    const int img = blockIdx.y;
    const int m0 = (mode == 0) ? min((int)blockIdx.x * 64, 216)
                               : min((int)blockIdx.x * 64, 160);
    const int wm = (wid & 1) * 32, wn = (wid >> 1) * 56;
    const int NC = (mode == 0) ? 7 : 9;

    const char *gBh, *gBl;
    if (mode == 0) {
        gBh = (const char*)(g_Xh + (size_t)img * 224 * 256);
        gBl = (const char*)(g_Xl + (size_t)img * 224 * 256);
    } else {
        gBh = (const char*)(g_Ph + (size_t)img * 224 * 256);
        gBl = (const char*)(g_Pl + (size_t)img * 224 * 256);
    }
    const char* gWh = (const char*)(g_Wh + (size_t)img * 224 * 64);
    const char* gWl = (const char*)(g_Wl + (size_t)img * 224 * 64);
    const float* xi = x + (size_t)img * H * H;

    float acc[2][7][4];
#pragma unroll
    for (int i = 0; i < 2; i++)
#pragma unroll
        for (int j = 0; j < 7; j++)
#pragma unroll
            for (int q = 0; q < 4; q++) acc[i][j][q] = 0.f;

    const uint32_t smb = smem_u32(sm);
    const uint32_t aab = smb + (uint32_t)(wm + (lane & 15)) * 80 + (lane >> 4) * 16;
    const uint32_t bab = smb + BOFF + (uint32_t)(wn + (lane & 7)) * 176
                       + ((lane >> 3) & 1) * 16 + (lane >> 4) * 64;

#define LOAD_CHUNK(CC, SB) do {                                                \
    const int c_ = (CC); const uint32_t sb_ = (SB);                            \
    const char *Ah_, *Al_, *Bh_, *Bl_; size_t arw_, brw_; int ko_;             \
    if (c_ < 7) { Ah_ = (const char*)g_G1h; Al_ = (const char*)g_G1l;          \
        arw_ = 512; Bh_ = gBh; Bl_ = gBl; brw_ = 512; ko_ = c_ * 64; }         \
    else { Ah_ = gWh; Al_ = gWl; arw_ = 128;                                   \
        Bh_ = (const char*)g_Cph; Bl_ = (const char*)g_Cpl; brw_ = 128;        \
        ko_ = (c_ - 7) * 64; }                                                 \
    { int r_ = tid >> 2, j_ = (tid & 3) * 16;                                  \
      size_t ga = (size_t)(m0 + r_) * arw_ + ko_ + j_;                         \
      cpa16(sb_ + r_ * 80 + j_, Ah_ + ga);                                     \
      cpa16(sb_ + ALS + r_ * 80 + j_, Al_ + ga); }                             \
    _Pragma("unroll")                                                          \
    for (int p_ = 0; p_ < 7; p_++) {                                           \
        int idx_ = tid + p_ * 256;                                             \
        int r_ = idx_ >> 3, q_ = idx_ & 7;                                     \
        size_t gb = (size_t)r_ * brw_ + ko_ + (q_ & 3) * 16;                   \
        const char* src_ = (q_ < 4) ? Bh_ : Bl_;                               \
        cpa16(sb_ + BOFF + r_ * 176 + (q_ >= 4 ? 64 : 0) + (q_ & 3) * 16,      \
              src_ + gb);                                                      \
    }                                                                          \
    asm volatile("cp.async.commit_group;" ::: "memory");                       \
} while (0)

    LOAD_CHUNK(0, smb);

#pragma unroll 1
    for (int c = 0; c < NC; c++) {
        asm volatile("cp.async.wait_group 0;" ::: "memory");
        __syncthreads();
        if (c + 1 < NC) LOAD_CHUNK(c + 1, smb + ((c + 1) & 1) * SST);

        const uint32_t off = (c & 1) * SST;
#pragma unroll
        for (int ks = 0; ks < 2; ks++) {
            const uint32_t ko = ks * 32;
            uint32_t ah[2][4], al[2][4];
#pragma unroll
            for (int i = 0; i < 2; i++) {
                ldsm4(ah[i], aab + off + i * 16 * 80 + ko);
                ldsm4(al[i], aab + off + i * 16 * 80 + ko + ALS);
            }
#pragma unroll
            for (int j = 0; j < 7; j++) {
                uint32_t b[4];
                ldsm4(b, bab + off + j * 8 * 176 + ko);
#pragma unroll
                for (int i = 0; i < 2; i++) {
                    mma16816(acc[i][j], ah[i], b);      // Ah*Bh
                    mma16816(acc[i][j], ah[i], b + 2);  // Ah*Bl
                    mma16816(acc[i][j], al[i], b);      // Al*Bh
                }
            }
        }
    }

#pragma unroll
    for (int i = 0; i < 2; i++) {
#pragma unroll
        for (int j = 0; j < 7; j++) {
            float* d = acc[i][j];
            int m1 = m0 + wm + 16 * i + (lane >> 2);
            int n  = wn + 8 * j + ((lane & 3) << 1);
            if (mode == 1) {
                const float* xr = xi + (size_t)m1 * H + n;
                float* orow = fout + (size_t)img * H * H + (size_t)m1 * H + n;
                float2 x0 = *(const float2*)xr;
                float2 x1 = *(const float2*)(xr + 8 * H);
                *(float2*)orow = make_float2(x0.x * d[0], x0.y * d[1]);
                *(float2*)(orow + 8 * H) = make_float2(x1.x * d[2], x1.y * d[3]);
            } else {
                store_PT(img, m1, n, d[0], d[1]);
                store_PT(img, m1 + 8, n, d[2], d[3]);
            }
        }
    }
}

// WK: fp32 per image: M2 = U.T^T, W = -C.M2 (cols 56-63 zero)
#define SU 228
#define STT 60
#define SMM 57
#define SCC 60
__global__ __launch_bounds__(256, 1)
void wk_kernel() {
    extern __shared__ float smw[];
    float* sU = smw;
    float* sT = sU + 56 * SU;
    float* sM = sT + 224 * STT;
    float* sC = sM + 56 * SMM;
    const int tid = threadIdx.x, wp = tid >> 5, ln = tid & 31;
    const int img = blockIdx.x;

    for (int idx = tid; idx < 56 * H; idx += 256) {
        int k = idx / H, w = idx - k * H;
        sU[k * SU + w] = g_D[idx];
    }
    for (int idx = tid; idx < H * 56; idx += 256) {
        int i = idx / 56, k = idx - i * 56;
        sC[i * SCC + k] = g_D[i * H + k];
    }
    const __half* Th = g_Th + (size_t)img * 56 * 256;
    const __half* Tl = g_Tl + (size_t)img * 56 * 256;
    for (int idx = tid; idx < 56 * H; idx += 256) {
        int l = idx / H, h = idx - l * H;
        sT[h * STT + l] = __half2float(Th[l * 256 + h]) + __half2float(Tl[l * 256 + h]);
    }
    __syncthreads();

    {
        const int k0 = wp * 7;
        float a0[7], a1[7];
#pragma unroll
        for (int ki = 0; ki < 7; ki++) { a0[ki] = 0.f; a1[ki] = 0.f; }
#pragma unroll 1
        for (int h4 = 0; h4 < 56; h4++) {
            const int h = h4 * 4;
            float4 u[7];
#pragma unroll
            for (int ki = 0; ki < 7; ki++)
                u[ki] = *reinterpret_cast<const float4*>(&sU[(k0 + ki) * SU + h]);
            const float* up = reinterpret_cast<const float*>(u);
#pragma unroll
            for (int dh = 0; dh < 4; dh++) {
                float t0 = sT[(h + dh) * STT + ln];
                float t1 = (ln < 24) ? sT[(h + dh) * STT + 32 + ln] : 0.f;
#pragma unroll
                for (int ki = 0; ki < 7; ki++) {
                    float uv = up[ki * 4 + dh];
                    a0[ki] += uv * t0;
                    a1[ki] += uv * t1;
                }
            }
        }
#pragma unroll
        for (int ki = 0; ki < 7; ki++) {
            sM[(k0 + ki) * SMM + ln] = a0[ki];
            if (ln < 24) sM[(k0 + ki) * SMM + 32 + ln] = a1[ki];
        }
    }
    __syncthreads();

    __half* Wh = g_Wh + (size_t)img * 224 * 64;
    __half* Wl = g_Wl + (size_t)img * 224 * 64;
#pragma unroll 1
    for (int it = 0; it < 4; it++) {
        const int i0 = wp * 28 + it * 7;
        float a0[7], a1[7];
#pragma unroll
        for (int ii = 0; ii < 7; ii++) { a0[ii] = 0.f; a1[ii] = 0.f; }
#pragma unroll 1
        for (int k4 = 0; k4 < 14; k4++) {
            const int k = k4 * 4;
            float4 u[7];
#pragma unroll
            for (int ii = 0; ii < 7; ii++)
                u[ii] = *reinterpret_cast<const float4*>(&sC[(i0 + ii) * SCC + k]);
            const float* up = reinterpret_cast<const float*>(u);
#pragma unroll
            for (int dk = 0; dk < 4; dk++) {
                float m0v = sM[(k + dk) * SMM + ln];
                float m1v = (ln < 24) ? sM[(k + dk) * SMM + 32 + ln] : 0.f;
#pragma unroll
                for (int ii = 0; ii < 7; ii++) {
                    float uv = up[ii * 4 + dk];
                    a0[ii] += uv * m0v;
                    a1[ii] += uv * m1v;
                }
            }
        }
#pragma unroll
        for (int ii = 0; ii < 7; ii++) {
            sp1(-a0[ii], &Wh[(i0 + ii) * 64 + ln], &Wl[(i0 + ii) * 64 + ln]);
            if (ln < 24) sp1(-a1[ii], &Wh[(i0 + ii) * 64 + 32 + ln], &Wl[(i0 + ii) * 64 + 32 + ln]);
        }
    }
    for (int idx = tid; idx < 224 * 8; idx += 256) {
        int r = idx >> 3, cz = 56 + (idx & 7);
        Wh[r * 64 + cz] = __float2half_rn(0.f);
        Wl[r * 64 + cz] = __float2half_rn(0.f);
    }
}

extern "C" void kernel_launch(void* const* d_in, const int* in_sizes, int n_in,
                              void* d_out, int out_size) {
    const float* x = (const float*)d_in[0];
    float* out = (float*)d_out;

    init_D_kernel<<<(H * H + 255) / 256, 256>>>();
    init_static_kernel<<<288, 256>>>();
    kxc_kernel<<<(int)(((size_t)NIMG * H * H / 4 + 255) / 256), 256>>>(x);

    const int smem = 2 * SST;  // 99328
    cudaFuncSetAttribute(gemm_kernel, cudaFuncAttributeMaxDynamicSharedMemorySize, smem);
    const int smw = (56 * SU + 224 * STT + 56 * SMM + 224 * SCC) * 4;
    cudaFuncSetAttribute(wk_kernel, cudaFuncAttributeMaxDynamicSharedMemorySize, smw);

    gemm_kernel<<<dim3(5, NIMG), 256, smem>>>(x, out, 0);
    wk_kernel<<<NIMG, 256, smw>>>();
    gemm_kernel<<<dim3(4, NIMG), 256, smem>>>(x, out, 1);
}

// round 17
// speedup vs baseline: 1.3414x; 1.0507x over previous
#include <cuda_runtime.h>
#include <cuda_fp16.h>
#include <math.h>
#include <stdint.h>

#define H 224
#define NIMG 1536
#define ASTG 9216            // A stage: 64 rows * 144 (hi 64B | lo 64B | pad 16)
#define ABASE 18432          // B region start (after 2 A stages)
#define BSTG 28672           // B stage: 224 rows * 128, XOR-swizzled

__device__ float g_D[H * H];
__device__ __half g_G1h[288 * 256], g_G1l[288 * 256];      // [A; U; 0]
__device__ __half g_Cph[224 * 64], g_Cpl[224 * 64];        // [C | 0]
__device__ __half g_Xh[NIMG * 224ULL * 256], g_Xl[NIMG * 224ULL * 256];
__device__ __half g_Ph[NIMG * 224ULL * 256], g_Pl[NIMG * 224ULL * 256];
__device__ __half g_Th[NIMG * 56ULL * 256],  g_Tl[NIMG * 56ULL * 256];
__device__ __half g_Wh[NIMG * 224ULL * 64],  g_Wl[NIMG * 224ULL * 64];

__global__ void init_D_kernel() {
    int idx = blockIdx.x * blockDim.x + threadIdx.x;
    if (idx >= H * H) return;
    int k = idx / H, i = idx - k * H;
    double v = cos(3.14159265358979323846 * (2.0 * i + 1.0) * (double)k / (2.0 * H))
             * sqrt(2.0 / (double)H);
    if (k == 0) v *= 0.70710678118654752440;
    g_D[idx] = (float)v;
}

__device__ __forceinline__ void sp1(float v, __half* ph, __half* pl) {
    __half h = __float2half_rn(v);
    *ph = h;
    *pl = __float2half_rn(v - __half2float(h));
}

__global__ __launch_bounds__(256)
void init_static_kernel() {
    __shared__ float srow[H];
    const int i = blockIdx.x, tid = threadIdx.x;
    if (i < 224)
        for (int k = tid; k < H; k += 256) srow[k] = g_D[i * H + k];
    __syncthreads();
    int j = tid;
    float v = 0.f;
    if (i < 224 && j < 224) {
        for (int k = 0; k < H; k++) v += srow[k] * g_D[k * H + j];
    } else if (i >= 224 && i < 280 && j < 224) {
        v = g_D[(i - 224) * H + j];
    }
    sp1(v, &g_G1h[i * 256 + j], &g_G1l[i * 256 + j]);
    if (i < 224 && tid < 64) {
        float c = (tid < 56) ? g_D[i * H + tid] : 0.f;
        sp1(c, &g_Cph[i * 64 + tid], &g_Cpl[i * 64 + tid]);
    }
}

__device__ __forceinline__ uint32_t psplit(float f0, float f1, uint32_t& lo) {
    __half h0 = __float2half_rn(f0), h1 = __float2half_rn(f1);
    __half2 lp = __floats2half2_rn(f0 - __half2float(h0), f1 - __half2float(h1));
    lo = *(uint32_t*)&lp;
    __half2 hp; hp.x = h0; hp.y = h1;
    return *(uint32_t*)&hp;
}

__global__ __launch_bounds__(256)
void kxc_kernel(const float* __restrict__ x) {
    size_t idx4 = ((size_t)blockIdx.x * 256 + threadIdx.x) * 4;
    if (idx4 >= (size_t)NIMG * H * H) return;
    size_t img = idx4 / (H * H);
    int rem = (int)(idx4 - img * (H * H));
    int h = rem / H, w = rem - h * H;
    float4 v = *(const float4*)(x + idx4);
    uint32_t l0, l1;
    uint32_t h0 = psplit(v.x, v.y, l0);
    uint32_t h1 = psplit(v.z, v.w, l1);
    size_t off = (img * H + h) * 256 + w;
    *(uint2*)(g_Xh + off) = make_uint2(h0, h1);
    *(uint2*)(g_Xl + off) = make_uint2(l0, l1);
}

__device__ __forceinline__ uint32_t smem_u32(const void* p) {
    uint32_t a;
    asm("{ .reg .u64 t; cvta.to.shared.u64 t, %1; cvt.u32.u64 %0, t; }" : "=r"(a) : "l"(p));
    return a;
}
__device__ __forceinline__ void ldsm4(uint32_t* r, uint32_t a) {
    asm volatile("ldmatrix.sync.aligned.m8n8.x4.shared.b16 {%0,%1,%2,%3}, [%4];"
                 : "=r"(r[0]), "=r"(r[1]), "=r"(r[2]), "=r"(r[3]) : "r"(a));
}
__device__ __forceinline__ void mma16816(float* d, const uint32_t* a, const uint32_t* b) {
    asm volatile("mma.sync.aligned.m16n8k16.row.col.f32.f16.f16.f32 "
                 "{%0,%1,%2,%3}, {%4,%5,%6,%7}, {%8,%9}, {%0,%1,%2,%3};"
                 : "+f"(d[0]), "+f"(d[1]), "+f"(d[2]), "+f"(d[3])
                 : "r"(a[0]), "r"(a[1]), "r"(a[2]), "r"(a[3]), "r"(b[0]), "r"(b[1]));
}
__device__ __forceinline__ void cpa16(uint32_t d, const void* s) {
    asm volatile("cp.async.cg.shared.global [%0], [%1], 16;" :: "r"(d), "l"(s));
}

__device__ __forceinline__ void store_PT(int img, int row, int n, float f0, float f1) {
    __half *oh, *ol;
    size_t base;
    if (row < 224)      { base = ((size_t)img * 224 + row) * 256 + n; oh = g_Ph; ol = g_Pl; }
    else if (row < 280) { base = ((size_t)img * 56 + (row - 224)) * 256 + n; oh = g_Th; ol = g_Tl; }
    else return;
    uint32_t lo;
    uint32_t hi = psplit(f0, f1, lo);
    *(uint32_t*)((char*)oh + base * 2) = hi;
    *(uint32_t*)((char*)ol + base * 2) = lo;
}

// mode 0 (K1): P'=[A;U].X^T, 5 m-tiles of 64, NC=7 -> P + T
// mode 1 (K4): G=A.P^T + W.C^T, 4 m-tiles of 64, NC=9 -> out = x*G
__global__ __launch_bounds__(256, 2)
void gemm_kernel(const float* __restrict__ x, float* __restrict__ fout, int mode) {
    extern __shared__ char sm[];
    const int tid = threadIdx.x, wid = tid >> 5, lane = tid & 31;
    const int img = blockIdx.y;
    const int m0 = (mode == 0) ? min((int)blockIdx.x * 64, 216)
                               : min((int)blockIdx.x * 64, 160);
    const int wm = (wid & 1) * 32, wn = (wid >> 1) * 56;
    const int NC = (mode == 0) ? 7 : 9;

    const char *gBh, *gBl;
    if (mode == 0) {
        gBh = (const char*)(g_Xh + (size_t)img * 224 * 256);
        gBl = (const char*)(g_Xl + (size_t)img * 224 * 256);
    } else {
        gBh = (const char*)(g_Ph + (size_t)img * 224 * 256);
        gBl = (const char*)(g_Pl + (size_t)img * 224 * 256);
    }
    const char* gWh = (const char*)(g_Wh + (size_t)img * 224 * 64);
    const char* gWl = (const char*)(g_Wl + (size_t)img * 224 * 64);
    const float* xi = x + (size_t)img * H * H;

    float acc[2][7][4];
#pragma unroll
    for (int i = 0; i < 2; i++)
#pragma unroll
        for (int j = 0; j < 7; j++)
#pragma unroll
            for (int q = 0; q < 4; q++) acc[i][j][q] = 0.f;

    const uint32_t smb = smem_u32(sm);
    // A lane address: row (wm + i*16 + (lane&15)), stride 144; hi at +0, lo at +64
    const uint32_t aab = smb + (uint32_t)(wm + (lane & 15)) * 144 + (lane >> 4) * 16;
    // B lane address pieces (swizzled): row base + 16*(u ^ (lane&7))
    const uint32_t brow = smb + ABASE + (uint32_t)(wn + (lane & 7)) * 128;
    const int bm = lane >> 3;                    // 0..3
    const int bu0 = (bm & 1) + ((bm & 2) ? 4 : 0);  // hi: 0,1  lo: 4,5
    const int bswz = lane & 7;

    // A loader: chunk c into A stage (c&1)
#define LOAD_A(CC) do {                                                        \
    const int c_ = (CC);                                                       \
    const uint32_t st_ = smb + ((uint32_t)(c_ & 1)) * ASTG;                    \
    const char *Ah_, *Al_; size_t arw_; int ko_;                               \
    if (c_ < 7) { Ah_ = (const char*)g_G1h; Al_ = (const char*)g_G1l;          \
                  arw_ = 512; ko_ = c_ * 64; }                                 \
    else { Ah_ = gWh; Al_ = gWl; arw_ = 128; ko_ = (c_ - 7) * 64; }            \
    _Pragma("unroll")                                                          \
    for (int p_ = 0; p_ < 2; p_++) {                                           \
        int idx_ = tid + p_ * 256;                                             \
        int r_ = idx_ >> 3, q_ = idx_ & 7;                                     \
        const char* src_ = (q_ < 4) ? (Ah_ + (size_t)(m0 + r_) * arw_ + ko_ + q_ * 16) \
                                    : (Al_ + (size_t)(m0 + r_) * arw_ + ko_ + (q_ - 4) * 16); \
        cpa16(st_ + r_ * 144 + q_ * 16, src_);                                 \
    }                                                                          \
    asm volatile("cp.async.commit_group;" ::: "memory");                       \
} while (0)

    // B loader: chunk c into B stage (c%3), XOR swizzle
#define LOAD_B(CC) do {                                                        \
    const int c_ = (CC);                                                       \
    const uint32_t st_ = smb + ABASE + ((uint32_t)(c_ % 3)) * BSTG;            \
    const char *Bh_, *Bl_; size_t brw_; int ko_;                               \
    if (c_ < 7) { Bh_ = gBh; Bl_ = gBl; brw_ = 512; ko_ = c_ * 64; }           \
    else { Bh_ = (const char*)g_Cph; Bl_ = (const char*)g_Cpl;                 \
           brw_ = 128; ko_ = (c_ - 7) * 64; }                                  \
    _Pragma("unroll")                                                          \
    for (int p_ = 0; p_ < 7; p_++) {                                           \
        int idx_ = tid + p_ * 256;                                             \
        int r_ = idx_ >> 3, q_ = idx_ & 7;                                     \
        const char* src_ = (q_ < 4) ? (Bh_ + (size_t)r_ * brw_ + ko_ + q_ * 16) \
                                    : (Bl_ + (size_t)r_ * brw_ + ko_ + (q_ - 4) * 16); \
        cpa16(st_ + r_ * 128 + ((q_ ^ (r_ & 7)) * 16), src_);                  \
    }                                                                          \
    asm volatile("cp.async.commit_group;" ::: "memory");                       \
} while (0)

    // prologue: [B0][A0][B1]
    LOAD_B(0);
    LOAD_A(0);
    LOAD_B(1);

#pragma unroll 1
    for (int c = 0; c < NC; c++) {
        if (c < NC - 1) asm volatile("cp.async.wait_group 1;" ::: "memory");
        else            asm volatile("cp.async.wait_group 0;" ::: "memory");
        __syncthreads();
        if (c + 1 < NC) LOAD_A(c + 1);
        if (c + 2 < NC) LOAD_B(c + 2);

        const uint32_t aoff = ((uint32_t)(c & 1)) * ASTG;
        const uint32_t boff = ((uint32_t)(c % 3)) * BSTG;
#pragma unroll
        for (int ks = 0; ks < 2; ks++) {
            uint32_t ah[2][4], al[2][4];
#pragma unroll
            for (int i = 0; i < 2; i++) {
                ldsm4(ah[i], aab + aoff + i * 16 * 144 + ks * 32);
                ldsm4(al[i], aab + aoff + i * 16 * 144 + ks * 32 + 64);
            }
            const int u = bu0 + 2 * ks;
#pragma unroll
            for (int j = 0; j < 7; j++) {
                uint32_t b[4];
                ldsm4(b, brow + boff + j * 8 * 128 + ((u ^ bswz) * 16));
#pragma unroll
                for (int i = 0; i < 2; i++) {
                    mma16816(acc[i][j], ah[i], b);      // Ah*Bh
                    mma16816(acc[i][j], ah[i], b + 2);  // Ah*Bl
                    mma16816(acc[i][j], al[i], b);      // Al*Bh
                }
            }
        }
    }

#pragma unroll
    for (int i = 0; i < 2; i++) {
#pragma unroll
        for (int j = 0; j < 7; j++) {
            float* d = acc[i][j];
            int m1 = m0 + wm + 16 * i + (lane >> 2);
            int n  = wn + 8 * j + ((lane & 3) << 1);
            if (mode == 1) {
                const float* xr = xi + (size_t)m1 * H + n;
                float* orow = fout + (size_t)img * H * H + (size_t)m1 * H + n;
                float2 x0 = *(const float2*)xr;
                float2 x1 = *(const float2*)(xr + 8 * H);
                *(float2*)orow = make_float2(x0.x * d[0], x0.y * d[1]);
                *(float2*)(orow + 8 * H) = make_float2(x1.x * d[2], x1.y * d[3]);
            } else {
                store_PT(img, m1, n, d[0], d[1]);
                store_PT(img, m1 + 8, n, d[2], d[3]);
            }
        }
    }
}

// WK: fp32 per image: M2 = U.T^T, W = -C.M2 (cols 56-63 zero)
#define SU 228
#define STT 60
#define SMM 57
#define SCC 60
__global__ __launch_bounds__(256, 1)
void wk_kernel() {
    extern __shared__ float smw[];
    float* sU = smw;
    float* sT = sU + 56 * SU;
    float* sM = sT + 224 * STT;
    float* sC = sM + 56 * SMM;
    const int tid = threadIdx.x, wp = tid >> 5, ln = tid & 31;
    const int img = blockIdx.x;

    for (int idx = tid; idx < 56 * H; idx += 256) {
        int k = idx / H, w = idx - k * H;
        sU[k * SU + w] = g_D[idx];
    }
    for (int idx = tid; idx < H * 56; idx += 256) {
        int i = idx / 56, k = idx - i * 56;
        sC[i * SCC + k] = g_D[i * H + k];
    }
    const __half* Th = g_Th + (size_t)img * 56 * 256;
    const __half* Tl = g_Tl + (size_t)img * 56 * 256;
    for (int idx = tid; idx < 56 * H; idx += 256) {
        int l = idx / H, h = idx - l * H;
        sT[h * STT + l] = __half2float(Th[l * 256 + h]) + __half2float(Tl[l * 256 + h]);
    }
    __syncthreads();

    {
        const int k0 = wp * 7;
        float a0[7], a1[7];
#pragma unroll
        for (int ki = 0; ki < 7; ki++) { a0[ki] = 0.f; a1[ki] = 0.f; }
#pragma unroll 1
        for (int h4 = 0; h4 < 56; h4++) {
            const int h = h4 * 4;
            float4 u[7];
#pragma unroll
            for (int ki = 0; ki < 7; ki++)
                u[ki] = *reinterpret_cast<const float4*>(&sU[(k0 + ki) * SU + h]);
            const float* up = reinterpret_cast<const float*>(u);
#pragma unroll
            for (int dh = 0; dh < 4; dh++) {
                float t0 = sT[(h + dh) * STT + ln];
                float t1 = (ln < 24) ? sT[(h + dh) * STT + 32 + ln] : 0.f;
#pragma unroll
                for (int ki = 0; ki < 7; ki++) {
                    float uv = up[ki * 4 + dh];
                    a0[ki] += uv * t0;
                    a1[ki] += uv * t1;
                }
            }
        }
#pragma unroll
        for (int ki = 0; ki < 7; ki++) {
            sM[(k0 + ki) * SMM + ln] = a0[ki];
            if (ln < 24) sM[(k0 + ki) * SMM + 32 + ln] = a1[ki];
        }
    }
    __syncthreads();

    __half* Wh = g_Wh + (size_t)img * 224 * 64;
    __half* Wl = g_Wl + (size_t)img * 224 * 64;
#pragma unroll 1
    for (int it = 0; it < 4; it++) {
        const int i0 = wp * 28 + it * 7;
        float a0[7], a1[7];
#pragma unroll
        for (int ii = 0; ii < 7; ii++) { a0[ii] = 0.f; a1[ii] = 0.f; }
#pragma unroll 1
        for (int k4 = 0; k4 < 14; k4++) {
            const int k = k4 * 4;
            float4 u[7];
#pragma unroll
            for (int ii = 0; ii < 7; ii++)
                u[ii] = *reinterpret_cast<const float4*>(&sC[(i0 + ii) * SCC + k]);
            const float* up = reinterpret_cast<const float*>(u);
#pragma unroll
            for (int dk = 0; dk < 4; dk++) {
                float m0v = sM[(k + dk) * SMM + ln];
                float m1v = (ln < 24) ? sM[(k + dk) * SMM + 32 + ln] : 0.f;
#pragma unroll
                for (int ii = 0; ii < 7; ii++) {
                    float uv = up[ii * 4 + dk];
                    a0[ii] += uv * m0v;
                    a1[ii] += uv * m1v;
                }
            }
        }
#pragma unroll
        for (int ii = 0; ii < 7; ii++) {
            sp1(-a0[ii], &Wh[(i0 + ii) * 64 + ln], &Wl[(i0 + ii) * 64 + ln]);
            if (ln < 24) sp1(-a1[ii], &Wh[(i0 + ii) * 64 + 32 + ln], &Wl[(i0 + ii) * 64 + 32 + ln]);
        }
    }
    for (int idx = tid; idx < 224 * 8; idx += 256) {
        int r = idx >> 3, cz = 56 + (idx & 7);
        Wh[r * 64 + cz] = __float2half_rn(0.f);
        Wl[r * 64 + cz] = __float2half_rn(0.f);
    }
}

extern "C" void kernel_launch(void* const* d_in, const int* in_sizes, int n_in,
                              void* d_out, int out_size) {
    const float* x = (const float*)d_in[0];
    float* out = (float*)d_out;

    init_D_kernel<<<(H * H + 255) / 256, 256>>>();
    init_static_kernel<<<288, 256>>>();
    kxc_kernel<<<(int)(((size_t)NIMG * H * H / 4 + 255) / 256), 256>>>(x);

    const int smem = ABASE + 3 * BSTG;  // 104448
    cudaFuncSetAttribute(gemm_kernel, cudaFuncAttributeMaxDynamicSharedMemorySize, smem);
    const int smw = (56 * SU + 224 * STT + 56 * SMM + 224 * SCC) * 4;
    cudaFuncSetAttribute(wk_kernel, cudaFuncAttributeMaxDynamicSharedMemorySize, smw);

    gemm_kernel<<<dim3(5, NIMG), 256, smem>>>(x, out, 0);
    wk_kernel<<<NIMG, 256, smw>>>();
    gemm_kernel<<<dim3(4, NIMG), 256, smem>>>(x, out, 1);
}